// round 6
// baseline (speedup 1.0000x reference)
#include <cuda_runtime.h>
#include <cuda_fp16.h>
#include <cstdint>

// ---------------- problem constants ----------------
#define N_    32
#define C_    128
#define H_    56
#define W_    56
#define K_    256
#define HW_   3136
#define PIX_  100352
#define KINP  1152      // 128*9
#define HP_   58
#define WP_   58

// ---------------- GEMM tiling ----------------
#define BM    128       // k-out per CTA
#define BN    64        // pixels per CTA
#define BK    64        // k-halves per stage
#define NSTEP 18        // 1152/64
#define PITCH 72        // halves per smem row (BK + 8) -> conflict-free
#define SA_BYTES (BM * PITCH * 2)               // 18432
#define STAGE_BYTES ((BM + BN) * PITCH * 2)     // 27648
#define SMEM_TOTAL  (2 * STAGE_BYTES)           // 55296  (x3 CTAs = 166KB)

// ---------------- scratch ----------------
__device__ alignas(1024) __half g_xp[(size_t)N_ * HP_ * WP_ * C_];
__device__ alignas(1024) __half g_wq[K_ * KINP];

// ---------------- helpers ----------------
__device__ __forceinline__ uint32_t smem_u32(const void* p) {
    uint32_t a;
    asm("{ .reg .u64 t; cvta.to.shared.u64 t, %1; cvt.u32.u64 %0, t; }" : "=r"(a) : "l"(p));
    return a;
}
#define CP16(dst, src) \
    asm volatile("cp.async.cg.shared.global [%0], [%1], 16;" :: "r"(dst), "l"(src) : "memory")
#define CP_COMMIT() asm volatile("cp.async.commit_group;" ::: "memory")
#define CP_WAIT0()  asm volatile("cp.async.wait_group 0;" ::: "memory")
#define LDSM_X4(r0, r1, r2, r3, addr) \
    asm volatile("ldmatrix.sync.aligned.m8n8.x4.shared.b16 {%0,%1,%2,%3}, [%4];" \
        : "=r"(r0), "=r"(r1), "=r"(r2), "=r"(r3) : "r"(addr))

__device__ __forceinline__ float quant16f(float x) {
    float r = rintf(x * 4096.0f);
    r = fminf(fmaxf(r, -32768.0f), 32767.0f);
    return r * (1.0f / 4096.0f);
}

// ---------------- prepass kernels ----------------
__global__ void zero_border_kernel() {
    int b = blockIdx.x;              // 32*58
    int n = b / HP_, hp = b % HP_;
    __half* rowp = g_xp + ((size_t)(n * HP_ + hp)) * WP_ * C_;
    uint4 z = make_uint4(0, 0, 0, 0);
    if (hp == 0 || hp == HP_ - 1) {
        for (int i = threadIdx.x; i < WP_ * C_ / 8; i += blockDim.x)
            reinterpret_cast<uint4*>(rowp)[i] = z;
    } else {
        if (threadIdx.x < 32) {
            int side = threadIdx.x >> 4;
            int q    = threadIdx.x & 15;
            __half* colp = rowp + (side ? (size_t)(WP_ - 1) * C_ : 0);
            reinterpret_cast<uint4*>(colp)[q] = z;
        }
    }
}

__global__ void xform_x_kernel(const float* __restrict__ x) {
    __shared__ __half st[W_ * C_];
    const int n = blockIdx.x, h = blockIdx.y;
    const int tid = threadIdx.x;
    const int c  = tid >> 1;
    const int wh = (tid & 1) * 28;
    const float* src = x + ((size_t)(n * C_ + c) * H_ + h) * W_ + wh;
    #pragma unroll
    for (int j = 0; j < 7; ++j) {
        float4 v = *reinterpret_cast<const float4*>(src + 4 * j);
        int wb = wh + 4 * j;
        st[(wb + 0) * C_ + c] = __float2half_rn(quant16f(v.x));
        st[(wb + 1) * C_ + c] = __float2half_rn(quant16f(v.y));
        st[(wb + 2) * C_ + c] = __float2half_rn(quant16f(v.z));
        st[(wb + 3) * C_ + c] = __float2half_rn(quant16f(v.w));
    }
    __syncthreads();
    __half* dst = g_xp + ((size_t)((n * HP_ + h + 1) * WP_ + 1)) * C_;
    for (int idx = tid; idx < W_ * C_ / 8; idx += 256) {
        int w = idx >> 4, q = idx & 15;
        reinterpret_cast<uint4*>(dst + (size_t)w * C_)[q] =
            reinterpret_cast<const uint4*>(st + w * C_)[q];
    }
}

__global__ void quant_w_kernel(const float* __restrict__ w) {
    int idx = blockIdx.x * 256 + threadIdx.x;
    if (idx >= K_ * KINP) return;
    int k = idx / KINP, t = idx % KINP;
    int rs = t >> 7, c = t & 127;
    float v = w[(size_t)(k * C_ + c) * 9 + rs];
    g_wq[idx] = __float2half_rn(quant16f(v));
}

// ---------------- main conv kernel: HMMA, 24 warps/SM ----------------
// grid (1568, 2), 256 threads, 3 CTAs/SM. CTA: 128 k-out x 64 pixels.
__global__ __launch_bounds__(256, 3) void conv_hmma_kernel(float* __restrict__ out) {
    extern __shared__ __align__(128) __half smem[];
    const uint32_t sbase = smem_u32(smem);

    const int tid  = threadIdx.x;
    const int lane = tid & 31;
    const int wid  = tid >> 5;          // 0..7
    const int warpM = wid & 3;          // 4 warps along M (32 rows each)
    const int warpN = wid >> 2;         // 2 warps along N (32 pixels each)
    const int g  = lane >> 2;
    const int tg = lane & 3;

    const int p0 = blockIdx.x * BN;
    const int k0 = blockIdx.y * BM;

    // ---- loader mapping ----
    // A: 128 rows x 8 chunks(16B); 2 thr/row, 4 alternating chunks each
    const int aRow = tid & 127;
    const int ac0  = tid >> 7;                       // chunks ac0 + 2j
    const __half* aG = g_wq + (size_t)(k0 + aRow) * KINP;
    // B: 64 rows x 8 chunks; 4 thr/row, 2 chunks each
    const int bRow = tid & 63;
    const int bc0  = tid >> 6;                       // chunks bc0, bc0+4
    const int bp  = p0 + bRow;
    const int bn  = bp / HW_;
    const int bhw = bp % HW_;
    const int bh  = bhw / W_;
    const int bw  = bhw % W_;
    const __half* bG = g_xp + ((size_t)((bn * HP_ + bh) * WP_ + bw)) * C_;

    // ---- fragment ldmatrix base addresses ----
    const uint32_t fragSel = ((lane & 15) * PITCH + ((lane >> 4) << 3)) * 2;
    const uint32_t aFragBase = sbase + (uint32_t)(warpM * 32 * PITCH * 2) + fragSel;
    const uint32_t bFragBase = sbase + (uint32_t)SA_BYTES
                             + (uint32_t)(warpN * 32 * PITCH * 2) + fragSel;

    float acc[2][4][4];
    #pragma unroll
    for (int i = 0; i < 2; ++i)
        #pragma unroll
        for (int j = 0; j < 4; ++j)
            #pragma unroll
            for (int e = 0; e < 4; ++e) acc[i][j][e] = 0.0f;

    auto load_stage = [&](int s) {
        const uint32_t sA = sbase + (s & 1) * STAGE_BYTES;
        const uint32_t sB = sA + SA_BYTES;
        const int rs = s >> 1;
        const int r  = (rs * 11) >> 5;               // rs/3 for rs<9
        const int ss = rs - 3 * r;
        const int ch = (s & 1 & 0) | ((s & 1) << 6); // (s&1)*64
        const __half* asrc = aG + s * BK;
        const __half* bsrc = bG + (r * WP_ + ss) * C_ + ch;
        #pragma unroll
        for (int j = 0; j < 4; ++j) {
            const int c = ac0 + 2 * j;
            CP16(sA + (aRow * PITCH + c * 8) * 2, asrc + c * 8);
        }
        #pragma unroll
        for (int j = 0; j < 2; ++j) {
            const int c = bc0 + 4 * j;
            CP16(sB + (bRow * PITCH + c * 8) * 2, bsrc + c * 8);
        }
    };

    auto compute = [&](int buf) {
        const uint32_t off = buf * STAGE_BYTES;
        #pragma unroll
        for (int kk = 0; kk < 4; ++kk) {
            const uint32_t kcb = kk * 32;            // 16 halves = 32 bytes
            uint32_t a[2][4], b[4][2];
            #pragma unroll
            for (int i = 0; i < 2; ++i)
                LDSM_X4(a[i][0], a[i][1], a[i][2], a[i][3],
                        aFragBase + off + kcb + i * (16 * PITCH * 2));
            #pragma unroll
            for (int jj = 0; jj < 2; ++jj)
                LDSM_X4(b[2 * jj][0], b[2 * jj + 1][0], b[2 * jj][1], b[2 * jj + 1][1],
                        bFragBase + off + kcb + jj * (16 * PITCH * 2));
            #pragma unroll
            for (int i = 0; i < 2; ++i)
                #pragma unroll
                for (int j = 0; j < 4; ++j)
                    asm volatile(
                        "mma.sync.aligned.m16n8k16.row.col.f32.f16.f16.f32 "
                        "{%0,%1,%2,%3}, {%4,%5,%6,%7}, {%8,%9}, {%0,%1,%2,%3};\n"
                        : "+f"(acc[i][j][0]), "+f"(acc[i][j][1]),
                          "+f"(acc[i][j][2]), "+f"(acc[i][j][3])
                        : "r"(a[i][0]), "r"(a[i][1]), "r"(a[i][2]), "r"(a[i][3]),
                          "r"(b[j][0]), "r"(b[j][1]));
        }
    };

    // ---- 2-stage pipeline, 1 barrier per stage ----
    load_stage(0); CP_COMMIT();

    #pragma unroll 1
    for (int s = 0; s < NSTEP; ++s) {
        CP_WAIT0();            // stage s landed (only group in flight)
        __syncthreads();       // all warps see stage s; all done with buf s^1
        if (s + 1 < NSTEP) { load_stage(s + 1); CP_COMMIT(); }
        compute(s & 1);
    }

    // ---- epilogue: registers -> gmem (NCHW) ----
    #pragma unroll
    for (int i = 0; i < 2; ++i) {
        const int kb = k0 + warpM * 32 + i * 16 + g;
        #pragma unroll
        for (int j = 0; j < 4; ++j) {
            const int pc = p0 + warpN * 32 + j * 8 + tg * 2;
            #pragma unroll
            for (int e = 0; e < 2; ++e) {
                const unsigned pe = (unsigned)(pc + e);
                const unsigned nn = pe / HW_;
                out[pe + (size_t)HW_ * (255u * nn + (unsigned)kb)]       = acc[i][j][e];
                out[pe + (size_t)HW_ * (255u * nn + (unsigned)(kb + 8))] = acc[i][j][2 + e];
            }
        }
    }
}

extern "C" void kernel_launch(void* const* d_in, const int* in_sizes, int n_in,
                              void* d_out, int out_size) {
    const float* x   = (const float*)d_in[0];   // (32,128,56,56) f32
    const float* wgt = (const float*)d_in[1];   // (256,128,3,3)  f32

    zero_border_kernel<<<N_ * HP_, 128>>>();
    xform_x_kernel<<<dim3(N_, H_), 256>>>(x);
    quant_w_kernel<<<(K_ * KINP + 255) / 256, 256>>>(wgt);

    static bool attr_set = false;
    if (!attr_set) {
        cudaFuncSetAttribute(conv_hmma_kernel,
                             cudaFuncAttributeMaxDynamicSharedMemorySize, SMEM_TOTAL);
        attr_set = true;
    }
    dim3 grid(PIX_ / BN, K_ / BM);              // (1568, 2)
    conv_hmma_kernel<<<grid, 256, SMEM_TOTAL>>>((float*)d_out);
}

// round 7
// speedup vs baseline: 1.0520x; 1.0520x over previous
#include <cuda_runtime.h>
#include <cuda_fp16.h>
#include <cstdint>

// ---------------- problem constants ----------------
#define N_    32
#define C_    128
#define H_    56
#define W_    56
#define K_    256
#define HW_   3136
#define PIX_  100352
#define KINP  1152      // 128*9
#define HP_   58
#define WP_   58

// ---------------- GEMM tiling ----------------
#define BM    128       // k-out per CTA
#define BN    128       // pixels per CTA
#define BK    64        // k-halves per stage
#define NSTEP 18        // 1152/64
#define PITCH 72        // halves per smem row -> conflict-free LDSM
#define SA_BYTES (BM * PITCH * 2)               // 18432
#define STAGE_BYTES ((BM + BN) * PITCH * 2)     // 36864
#define NBUF  4
#define SMEM_TOTAL (NBUF * STAGE_BYTES)         // 147456

// ---------------- scratch ----------------
__device__ alignas(1024) __half g_xp[(size_t)N_ * HP_ * WP_ * C_];
__device__ alignas(1024) __half g_wq[K_ * KINP];

// ---------------- helpers ----------------
__device__ __forceinline__ uint32_t smem_u32(const void* p) {
    uint32_t a;
    asm("{ .reg .u64 t; cvta.to.shared.u64 t, %1; cvt.u32.u64 %0, t; }" : "=r"(a) : "l"(p));
    return a;
}
#define CP16(dst, src) \
    asm volatile("cp.async.cg.shared.global [%0], [%1], 16;" :: "r"(dst), "l"(src) : "memory")
#define CP_COMMIT() asm volatile("cp.async.commit_group;" ::: "memory")
#define CP_WAITN(n) asm volatile("cp.async.wait_group %0;" :: "n"(n) : "memory")
#define LDSM_X4(r0, r1, r2, r3, addr) \
    asm volatile("ldmatrix.sync.aligned.m8n8.x4.shared.b16 {%0,%1,%2,%3}, [%4];" \
        : "=r"(r0), "=r"(r1), "=r"(r2), "=r"(r3) : "r"(addr))

__device__ __forceinline__ float quant16f(float x) {
    float r = rintf(x * 4096.0f);
    r = fminf(fmaxf(r, -32768.0f), 32767.0f);
    return r * (1.0f / 4096.0f);
}

// ---------------- prepass kernels ----------------
__global__ void zero_border_kernel() {
    int b = blockIdx.x;              // 32*58
    int n = b / HP_, hp = b % HP_;
    __half* rowp = g_xp + ((size_t)(n * HP_ + hp)) * WP_ * C_;
    uint4 z = make_uint4(0, 0, 0, 0);
    if (hp == 0 || hp == HP_ - 1) {
        for (int i = threadIdx.x; i < WP_ * C_ / 8; i += blockDim.x)
            reinterpret_cast<uint4*>(rowp)[i] = z;
    } else {
        if (threadIdx.x < 32) {
            int side = threadIdx.x >> 4;
            int q    = threadIdx.x & 15;
            __half* colp = rowp + (side ? (size_t)(WP_ - 1) * C_ : 0);
            reinterpret_cast<uint4*>(colp)[q] = z;
        }
    }
}

__global__ void xform_x_kernel(const float* __restrict__ x) {
    __shared__ __half st[W_ * C_];
    const int n = blockIdx.x, h = blockIdx.y;
    const int tid = threadIdx.x;
    const int c  = tid >> 1;
    const int wh = (tid & 1) * 28;
    const float* src = x + ((size_t)(n * C_ + c) * H_ + h) * W_ + wh;
    #pragma unroll
    for (int j = 0; j < 7; ++j) {
        float4 v = *reinterpret_cast<const float4*>(src + 4 * j);
        int wb = wh + 4 * j;
        st[(wb + 0) * C_ + c] = __float2half_rn(quant16f(v.x));
        st[(wb + 1) * C_ + c] = __float2half_rn(quant16f(v.y));
        st[(wb + 2) * C_ + c] = __float2half_rn(quant16f(v.z));
        st[(wb + 3) * C_ + c] = __float2half_rn(quant16f(v.w));
    }
    __syncthreads();
    __half* dst = g_xp + ((size_t)((n * HP_ + h + 1) * WP_ + 1)) * C_;
    for (int idx = tid; idx < W_ * C_ / 8; idx += 256) {
        int w = idx >> 4, q = idx & 15;
        reinterpret_cast<uint4*>(dst + (size_t)w * C_)[q] =
            reinterpret_cast<const uint4*>(st + w * C_)[q];
    }
}

__global__ void quant_w_kernel(const float* __restrict__ w) {
    int idx = blockIdx.x * 256 + threadIdx.x;
    if (idx >= K_ * KINP) return;
    int k = idx / KINP, t = idx % KINP;
    int rs = t >> 7, c = t & 127;
    float v = w[(size_t)(k * C_ + c) * 9 + rs];
    g_wq[idx] = __float2half_rn(quant16f(v));
}

// ---------------- main conv kernel ----------------
// 512 threads, 16 warps (4x4), warp tile 32x32, fragment double buffering,
// 4-stage cp.async pipeline (3 loads in flight).
__global__ __launch_bounds__(512, 1) void conv_hmma_kernel(float* __restrict__ out) {
    extern __shared__ __align__(128) __half smem[];
    const uint32_t sbase = smem_u32(smem);

    const int tid  = threadIdx.x;
    const int lane = tid & 31;
    const int wid  = tid >> 5;          // 0..15
    const int warpM = wid & 3;          // 4 warps along M (32 rows each)
    const int warpN = wid >> 2;         // 4 warps along N (32 px each)
    const int g  = lane >> 2;
    const int tg = lane & 3;

    const int p0 = blockIdx.x * BN;
    const int k0 = blockIdx.y * BM;

    // ---- loader mapping: 128 rows x 8 chunks per operand; 2 chunks/thread each ----
    const int ldRow = tid & 127;
    const int c0    = tid >> 7;                      // 0..3; chunks c0, c0+4
    const __half* aG = g_wq + (size_t)(k0 + ldRow) * KINP;
    const int bp  = p0 + ldRow;
    const int bn  = bp / HW_;
    const int bhw = bp % HW_;
    const int bh  = bhw / W_;
    const int bw  = bhw % W_;
    const __half* bG = g_xp + ((size_t)((bn * HP_ + bh) * WP_ + bw)) * C_;

    // ---- fragment ldmatrix base addresses ----
    const uint32_t fragSel = ((lane & 15) * PITCH + ((lane >> 4) << 3)) * 2;
    const uint32_t aFragBase = sbase + (uint32_t)(warpM * 32 * PITCH * 2) + fragSel;
    const uint32_t bFragBase = sbase + (uint32_t)SA_BYTES
                             + (uint32_t)(warpN * 32 * PITCH * 2) + fragSel;

    float acc[2][4][4];
    #pragma unroll
    for (int i = 0; i < 2; ++i)
        #pragma unroll
        for (int j = 0; j < 4; ++j)
            #pragma unroll
            for (int e = 0; e < 4; ++e) acc[i][j][e] = 0.0f;

    // double-buffered fragments
    uint32_t fa[2][8];   // [buf][i*4 + r]: two m16 tiles
    uint32_t fb[2][8];   // [buf][half*4 + r]: four n8 tiles (two LDSM.x4)

    auto load_stage = [&](int s) {
        const uint32_t sA = sbase + (uint32_t)((s & (NBUF - 1)) * STAGE_BYTES);
        const uint32_t sB = sA + SA_BYTES;
        const int rs = s >> 1;
        const int r  = (rs * 11) >> 5;               // rs/3 for rs<9
        const int ss = rs - 3 * r;
        const int ch = (s & 1) << 6;
        const __half* asrc = aG + s * BK;
        const __half* bsrc = bG + (r * WP_ + ss) * C_ + ch;
        #pragma unroll
        for (int j = 0; j < 2; ++j) {
            const int c = c0 + 4 * j;
            CP16(sA + (ldRow * PITCH + c * 8) * 2, asrc + c * 8);
            CP16(sB + (ldRow * PITCH + c * 8) * 2, bsrc + c * 8);
        }
    };

    auto ldfrag = [&](uint32_t off, int kk, int rb) {
        const uint32_t kcb = (uint32_t)(kk * 32);    // 16 halves = 32B
        LDSM_X4(fa[rb][0], fa[rb][1], fa[rb][2], fa[rb][3],
                aFragBase + off + kcb);
        LDSM_X4(fa[rb][4], fa[rb][5], fa[rb][6], fa[rb][7],
                aFragBase + off + kcb + 16 * PITCH * 2);
        LDSM_X4(fb[rb][0], fb[rb][1], fb[rb][2], fb[rb][3],
                bFragBase + off + kcb);
        LDSM_X4(fb[rb][4], fb[rb][5], fb[rb][6], fb[rb][7],
                bFragBase + off + kcb + 16 * PITCH * 2);
    };

    auto mma_kk = [&](int rb) {
        #pragma unroll
        for (int i = 0; i < 2; ++i) {
            const uint32_t* a = &fa[rb][i * 4];
            #pragma unroll
            for (int j = 0; j < 4; ++j) {
                // n-tile j: regs (j>>1)*4 + (j&1) and +2   (k0-7, k8-15)
                const uint32_t b0 = fb[rb][(j >> 1) * 4 + (j & 1)];
                const uint32_t b1 = fb[rb][(j >> 1) * 4 + (j & 1) + 2];
                asm volatile(
                    "mma.sync.aligned.m16n8k16.row.col.f32.f16.f16.f32 "
                    "{%0,%1,%2,%3}, {%4,%5,%6,%7}, {%8,%9}, {%0,%1,%2,%3};\n"
                    : "+f"(acc[i][j][0]), "+f"(acc[i][j][1]),
                      "+f"(acc[i][j][2]), "+f"(acc[i][j][3])
                    : "r"(a[0]), "r"(a[1]), "r"(a[2]), "r"(a[3]),
                      "r"(b0), "r"(b1));
            }
        }
    };

    // ---- prologue: 3 stages in flight ----
    load_stage(0); CP_COMMIT();
    load_stage(1); CP_COMMIT();
    load_stage(2); CP_COMMIT();

    #pragma unroll 1
    for (int s = 0; s < NSTEP; ++s) {
        if (s < NSTEP - 2)      { CP_WAITN(2); }
        else if (s == NSTEP - 2){ CP_WAITN(1); }
        else                    { CP_WAITN(0); }
        __syncthreads();                       // stage s visible; buf (s+3)%4 free

        const uint32_t off = (uint32_t)((s & (NBUF - 1)) * STAGE_BYTES);
        ldfrag(off, 0, 0);                     // start fragment stream ASAP
        if (s + 3 < NSTEP) { load_stage(s + 3); CP_COMMIT(); }

        #pragma unroll
        for (int kk = 0; kk < 4; ++kk) {
            const int cur = kk & 1;
            if (kk < 3) ldfrag(off, kk + 1, cur ^ 1);   // prefetch next frags
            mma_kk(cur);
        }
    }

    // ---- epilogue: registers -> gmem (NCHW) ----
    #pragma unroll
    for (int i = 0; i < 2; ++i) {
        const int kb = k0 + warpM * 32 + i * 16 + g;
        #pragma unroll
        for (int j = 0; j < 4; ++j) {
            const int pc = p0 + warpN * 32 + j * 8 + tg * 2;
            #pragma unroll
            for (int e = 0; e < 2; ++e) {
                const unsigned pe = (unsigned)(pc + e);
                const unsigned nn = pe / HW_;
                out[pe + (size_t)HW_ * (255u * nn + (unsigned)kb)]       = acc[i][j][e];
                out[pe + (size_t)HW_ * (255u * nn + (unsigned)(kb + 8))] = acc[i][j][2 + e];
            }
        }
    }
}

extern "C" void kernel_launch(void* const* d_in, const int* in_sizes, int n_in,
                              void* d_out, int out_size) {
    const float* x   = (const float*)d_in[0];   // (32,128,56,56) f32
    const float* wgt = (const float*)d_in[1];   // (256,128,3,3)  f32

    zero_border_kernel<<<N_ * HP_, 128>>>();
    xform_x_kernel<<<dim3(N_, H_), 256>>>(x);
    quant_w_kernel<<<(K_ * KINP + 255) / 256, 256>>>(wgt);

    static bool attr_set = false;
    if (!attr_set) {
        cudaFuncSetAttribute(conv_hmma_kernel,
                             cudaFuncAttributeMaxDynamicSharedMemorySize, SMEM_TOTAL);
        attr_set = true;
    }
    dim3 grid(PIX_ / BN, K_ / BM);              // (784, 2)
    conv_hmma_kernel<<<grid, 512, SMEM_TOTAL>>>((float*)d_out);
}

// round 8
// speedup vs baseline: 1.1537x; 1.0967x over previous
#include <cuda_runtime.h>
#include <cuda_fp16.h>
#include <cstdint>

// ---------------- problem constants ----------------
#define N_    32
#define C_    128
#define H_    56
#define W_    56
#define K_    256
#define HW_   3136
#define PIX_  100352
#define KINP  1152      // 128*9
#define HP_   58
#define WP_   58

// ---------------- GEMM tiling ----------------
#define BM    128       // k-out per CTA
#define BN    256       // pixels per CTA
#define BK    64        // k-halves per stage
#define NSTEP 18        // 1152/64
#define PITCH 72        // halves per smem row -> conflict-free LDSM
#define SA_BYTES (BM * PITCH * 2)               // 18432
#define SB_BYTES (BN * PITCH * 2)               // 36864
#define STAGE_BYTES (SA_BYTES + SB_BYTES)       // 55296
#define NBUF  3
#define SMEM_TOTAL (NBUF * STAGE_BYTES)         // 165888

// ---------------- scratch ----------------
__device__ alignas(1024) __half g_xp[(size_t)N_ * HP_ * WP_ * C_];
__device__ alignas(1024) __half g_wq[K_ * KINP];

// ---------------- helpers ----------------
__device__ __forceinline__ uint32_t smem_u32(const void* p) {
    uint32_t a;
    asm("{ .reg .u64 t; cvta.to.shared.u64 t, %1; cvt.u32.u64 %0, t; }" : "=r"(a) : "l"(p));
    return a;
}
#define CP16(dst, src) \
    asm volatile("cp.async.cg.shared.global [%0], [%1], 16;" :: "r"(dst), "l"(src) : "memory")
#define CP_COMMIT() asm volatile("cp.async.commit_group;" ::: "memory")
#define CP_WAIT1()  asm volatile("cp.async.wait_group 1;" ::: "memory")
#define CP_WAIT0()  asm volatile("cp.async.wait_group 0;" ::: "memory")
#define LDSM_X4(r0, r1, r2, r3, addr) \
    asm volatile("ldmatrix.sync.aligned.m8n8.x4.shared.b16 {%0,%1,%2,%3}, [%4];" \
        : "=r"(r0), "=r"(r1), "=r"(r2), "=r"(r3) : "r"(addr))

__device__ __forceinline__ float quant16f(float x) {
    float r = rintf(x * 4096.0f);
    r = fminf(fmaxf(r, -32768.0f), 32767.0f);
    return r * (1.0f / 4096.0f);
}

// ---------------- prepass kernels ----------------
__global__ void zero_border_kernel() {
    int b = blockIdx.x;              // 32*58
    int n = b / HP_, hp = b % HP_;
    __half* rowp = g_xp + ((size_t)(n * HP_ + hp)) * WP_ * C_;
    uint4 z = make_uint4(0, 0, 0, 0);
    if (hp == 0 || hp == HP_ - 1) {
        for (int i = threadIdx.x; i < WP_ * C_ / 8; i += blockDim.x)
            reinterpret_cast<uint4*>(rowp)[i] = z;
    } else {
        if (threadIdx.x < 32) {
            int side = threadIdx.x >> 4;
            int q    = threadIdx.x & 15;
            __half* colp = rowp + (side ? (size_t)(WP_ - 1) * C_ : 0);
            reinterpret_cast<uint4*>(colp)[q] = z;
        }
    }
}

__global__ void xform_x_kernel(const float* __restrict__ x) {
    __shared__ __half st[W_ * C_];
    const int n = blockIdx.x, h = blockIdx.y;
    const int tid = threadIdx.x;
    const int c  = tid >> 1;
    const int wh = (tid & 1) * 28;
    const float* src = x + ((size_t)(n * C_ + c) * H_ + h) * W_ + wh;
    #pragma unroll
    for (int j = 0; j < 7; ++j) {
        float4 v = *reinterpret_cast<const float4*>(src + 4 * j);
        int wb = wh + 4 * j;
        st[(wb + 0) * C_ + c] = __float2half_rn(quant16f(v.x));
        st[(wb + 1) * C_ + c] = __float2half_rn(quant16f(v.y));
        st[(wb + 2) * C_ + c] = __float2half_rn(quant16f(v.z));
        st[(wb + 3) * C_ + c] = __float2half_rn(quant16f(v.w));
    }
    __syncthreads();
    __half* dst = g_xp + ((size_t)((n * HP_ + h + 1) * WP_ + 1)) * C_;
    for (int idx = tid; idx < W_ * C_ / 8; idx += 256) {
        int w = idx >> 4, q = idx & 15;
        reinterpret_cast<uint4*>(dst + (size_t)w * C_)[q] =
            reinterpret_cast<const uint4*>(st + w * C_)[q];
    }
}

__global__ void quant_w_kernel(const float* __restrict__ w) {
    int idx = blockIdx.x * 256 + threadIdx.x;
    if (idx >= K_ * KINP) return;
    int k = idx / KINP, t = idx % KINP;
    int rs = t >> 7, c = t & 127;
    float v = w[(size_t)(k * C_ + c) * 9 + rs];
    g_wq[idx] = __float2half_rn(quant16f(v));
}

// ---------------- main conv kernel ----------------
// 256 threads, 8 warps (2x4), warp tile 64x64 (CUTLASS shape).
// CTA: 128 k-out x 256 pixels, K loop 18 x BK=64, 3-stage cp.async.
__global__ __launch_bounds__(256, 1) void conv_hmma_kernel(float* __restrict__ out) {
    extern __shared__ __align__(128) __half smem[];
    const uint32_t sbase = smem_u32(smem);

    const int tid  = threadIdx.x;
    const int lane = tid & 31;
    const int wid  = tid >> 5;          // 0..7
    const int warpM = wid & 1;          // 2 warps along M (64 rows each)
    const int warpN = wid >> 1;         // 4 warps along N (64 px each)
    const int g  = lane >> 2;
    const int tg = lane & 3;

    const int p0 = blockIdx.x * BN;
    const int k0 = blockIdx.y * BM;

    // ---- loader mapping ----
    // A: 128 rows, 2 thr/row, 4 contiguous 16B chunks each
    const int aRow = tid >> 1;
    const int ac0  = (tid & 1) * 4;
    const __half* aG = g_wq + (size_t)(k0 + aRow) * KINP;
    // B: 256 rows, 1 thr/row, all 8 chunks (full 128B row per thread)
    const int bRow = tid;
    const int bp  = p0 + bRow;
    const int bn  = bp / HW_;
    const int bhw = bp % HW_;
    const int bh  = bhw / W_;
    const int bw  = bhw % W_;
    const __half* bG = g_xp + ((size_t)((bn * HP_ + bh) * WP_ + bw)) * C_;

    // ---- fragment ldmatrix base addresses ----
    const uint32_t fragSel = ((lane & 15) * PITCH + ((lane >> 4) << 3)) * 2;
    const uint32_t aFragBase = sbase + (uint32_t)(warpM * 64 * PITCH * 2) + fragSel;
    const uint32_t bFragBase = sbase + (uint32_t)SA_BYTES
                             + (uint32_t)(warpN * 64 * PITCH * 2) + fragSel;

    float acc[4][8][4];
    #pragma unroll
    for (int i = 0; i < 4; ++i)
        #pragma unroll
        for (int j = 0; j < 8; ++j)
            #pragma unroll
            for (int e = 0; e < 4; ++e) acc[i][j][e] = 0.0f;

    auto load_stage = [&](int s) {
        const uint32_t sA = sbase + (uint32_t)((s % NBUF) * STAGE_BYTES);
        const uint32_t sB = sA + SA_BYTES;
        const int rs = s >> 1;
        const int r  = (rs * 11) >> 5;               // rs/3 for rs<9
        const int ss = rs - 3 * r;
        const int ch = (s & 1) << 6;
        const __half* asrc = aG + s * BK;
        const __half* bsrc = bG + (r * WP_ + ss) * C_ + ch;
        #pragma unroll
        for (int j = 0; j < 4; ++j) {
            const int c = ac0 + j;
            CP16(sA + (aRow * PITCH + c * 8) * 2, asrc + c * 8);
        }
        #pragma unroll
        for (int j = 0; j < 8; ++j)
            CP16(sB + (bRow * PITCH + j * 8) * 2, bsrc + j * 8);
    };

    auto compute = [&](int buf) {
        const uint32_t off = (uint32_t)(buf * STAGE_BYTES);
        #pragma unroll
        for (int kk = 0; kk < 4; ++kk) {
            const uint32_t kcb = (uint32_t)(kk * 32);   // 16 halves = 32B
            uint32_t a[4][4], b[8][2];
            #pragma unroll
            for (int i = 0; i < 4; ++i)
                LDSM_X4(a[i][0], a[i][1], a[i][2], a[i][3],
                        aFragBase + off + kcb + i * (16 * PITCH * 2));
            #pragma unroll
            for (int jj = 0; jj < 4; ++jj)
                LDSM_X4(b[2 * jj][0], b[2 * jj + 1][0], b[2 * jj][1], b[2 * jj + 1][1],
                        bFragBase + off + kcb + jj * (16 * PITCH * 2));
            #pragma unroll
            for (int i = 0; i < 4; ++i)
                #pragma unroll
                for (int j = 0; j < 8; ++j)
                    asm volatile(
                        "mma.sync.aligned.m16n8k16.row.col.f32.f16.f16.f32 "
                        "{%0,%1,%2,%3}, {%4,%5,%6,%7}, {%8,%9}, {%0,%1,%2,%3};\n"
                        : "+f"(acc[i][j][0]), "+f"(acc[i][j][1]),
                          "+f"(acc[i][j][2]), "+f"(acc[i][j][3])
                        : "r"(a[i][0]), "r"(a[i][1]), "r"(a[i][2]), "r"(a[i][3]),
                          "r"(b[j][0]), "r"(b[j][1]));
        }
    };

    // ---- 3-stage pipeline (R4-proven schedule) ----
    load_stage(0); CP_COMMIT();
    load_stage(1); CP_COMMIT();

    #pragma unroll 1
    for (int s = 0; s < NSTEP; ++s) {
        if (s < NSTEP - 1) { CP_WAIT1(); } else { CP_WAIT0(); }
        __syncthreads();                 // stage s visible; buf (s+2)%3 free
        if (s + 2 < NSTEP) { load_stage(s + 2); CP_COMMIT(); }
        compute(s % NBUF);
    }

    // ---- epilogue: registers -> gmem (NCHW) ----
    #pragma unroll
    for (int i = 0; i < 4; ++i) {
        const int kb = k0 + warpM * 64 + i * 16 + g;
        #pragma unroll
        for (int j = 0; j < 8; ++j) {
            const int pc = p0 + warpN * 64 + j * 8 + tg * 2;
            #pragma unroll
            for (int e = 0; e < 2; ++e) {
                const unsigned pe = (unsigned)(pc + e);
                const unsigned nn = pe / HW_;
                out[pe + (size_t)HW_ * (255u * nn + (unsigned)kb)]       = acc[i][j][e];
                out[pe + (size_t)HW_ * (255u * nn + (unsigned)(kb + 8))] = acc[i][j][2 + e];
            }
        }
    }
}

extern "C" void kernel_launch(void* const* d_in, const int* in_sizes, int n_in,
                              void* d_out, int out_size) {
    const float* x   = (const float*)d_in[0];   // (32,128,56,56) f32
    const float* wgt = (const float*)d_in[1];   // (256,128,3,3)  f32

    zero_border_kernel<<<N_ * HP_, 128>>>();
    xform_x_kernel<<<dim3(N_, H_), 256>>>(x);
    quant_w_kernel<<<(K_ * KINP + 255) / 256, 256>>>(wgt);

    static bool attr_set = false;
    if (!attr_set) {
        cudaFuncSetAttribute(conv_hmma_kernel,
                             cudaFuncAttributeMaxDynamicSharedMemorySize, SMEM_TOTAL);
        attr_set = true;
    }
    dim3 grid(PIX_ / BN, K_ / BM);              // (392, 2)
    conv_hmma_kernel<<<grid, 256, SMEM_TOTAL>>>((float*)d_out);
}

// round 10
// speedup vs baseline: 1.4345x; 1.2434x over previous
#include <cuda_runtime.h>
#include <cuda_fp16.h>
#include <cstdint>

// ---------------- problem constants ----------------
#define N_    32
#define C_    128
#define H_    56
#define W_    56
#define K_    256
#define HW_   3136
#define HP_   58
#define WP_   58
#define TPI   784            // winograd tiles per image (28*28)
#define P_TOT 25088          // 32 * 784

// ---------------- GEMM tiling (per xi: M=256, N=25088, K=128) ----------------
#define GBM   256
#define GBN   128
#define GBK   64
#define PITCH 72
#define SA_BYTES (GBM * PITCH * 2)              // 36864
#define SB_BYTES (GBN * PITCH * 2)              // 18432
#define STAGE_BYTES (SA_BYTES + SB_BYTES)       // 55296
#define SMEM_TOTAL (2 * STAGE_BYTES)            // 110592

// ---------------- scratch ----------------
__device__ alignas(1024) __half g_xp[(size_t)N_ * HP_ * WP_ * C_];       // padded NHWC fp16
__device__ alignas(1024) __half g_U[16 * K_ * C_];                       // wino weights [xi][k][c]
__device__ alignas(1024) __half g_V[(size_t)16 * P_TOT * C_];            // wino inputs  [xi][p][c]
__device__ alignas(1024) __half g_M[(size_t)16 * K_ * P_TOT];            // wino products [xi][k][p]

// ---------------- helpers ----------------
__device__ __forceinline__ uint32_t smem_u32(const void* p) {
    uint32_t a;
    asm("{ .reg .u64 t; cvta.to.shared.u64 t, %1; cvt.u32.u64 %0, t; }" : "=r"(a) : "l"(p));
    return a;
}
#define CP16(dst, src) \
    asm volatile("cp.async.cg.shared.global [%0], [%1], 16;" :: "r"(dst), "l"(src) : "memory")
#define CP_COMMIT() asm volatile("cp.async.commit_group;" ::: "memory")
#define CP_WAIT1()  asm volatile("cp.async.wait_group 1;" ::: "memory")
#define CP_WAIT0()  asm volatile("cp.async.wait_group 0;" ::: "memory")
#define LDSM_X4(r0, r1, r2, r3, addr) \
    asm volatile("ldmatrix.sync.aligned.m8n8.x4.shared.b16 {%0,%1,%2,%3}, [%4];" \
        : "=r"(r0), "=r"(r1), "=r"(r2), "=r"(r3) : "r"(addr))

__device__ __forceinline__ float quant16f(float x) {
    float r = rintf(x * 4096.0f);
    r = fminf(fmaxf(r, -32768.0f), 32767.0f);
    return r * (1.0f / 4096.0f);
}

// ---------------- prepass: quantize + pad input ----------------
__global__ void zero_border_kernel() {
    int b = blockIdx.x;              // 32*58
    int n = b / HP_, hp = b % HP_;
    __half* rowp = g_xp + ((size_t)(n * HP_ + hp)) * WP_ * C_;
    uint4 z = make_uint4(0, 0, 0, 0);
    if (hp == 0 || hp == HP_ - 1) {
        for (int i = threadIdx.x; i < WP_ * C_ / 8; i += blockDim.x)
            reinterpret_cast<uint4*>(rowp)[i] = z;
    } else {
        if (threadIdx.x < 32) {
            int side = threadIdx.x >> 4;
            int q    = threadIdx.x & 15;
            __half* colp = rowp + (side ? (size_t)(WP_ - 1) * C_ : 0);
            reinterpret_cast<uint4*>(colp)[q] = z;
        }
    }
}

__global__ void xform_x_kernel(const float* __restrict__ x) {
    __shared__ __half st[W_ * C_];
    const int n = blockIdx.x, h = blockIdx.y;
    const int tid = threadIdx.x;
    const int c  = tid >> 1;
    const int wh = (tid & 1) * 28;
    const float* src = x + ((size_t)(n * C_ + c) * H_ + h) * W_ + wh;
    #pragma unroll
    for (int j = 0; j < 7; ++j) {
        float4 v = *reinterpret_cast<const float4*>(src + 4 * j);
        int wb = wh + 4 * j;
        st[(wb + 0) * C_ + c] = __float2half_rn(quant16f(v.x));
        st[(wb + 1) * C_ + c] = __float2half_rn(quant16f(v.y));
        st[(wb + 2) * C_ + c] = __float2half_rn(quant16f(v.z));
        st[(wb + 3) * C_ + c] = __float2half_rn(quant16f(v.w));
    }
    __syncthreads();
    __half* dst = g_xp + ((size_t)((n * HP_ + h + 1) * WP_ + 1)) * C_;
    for (int idx = tid; idx < W_ * C_ / 8; idx += 256) {
        int w = idx >> 4, q = idx & 15;
        reinterpret_cast<uint4*>(dst + (size_t)w * C_)[q] =
            reinterpret_cast<const uint4*>(st + w * C_)[q];
    }
}

// ---------------- weight transform: U = G g G^T (exact in f32) ----------------
__global__ void wino_w_kernel(const float* __restrict__ w) {
    int idx = blockIdx.x * 256 + threadIdx.x;      // (k, c)
    if (idx >= K_ * C_) return;
    const float* gp = w + (size_t)idx * 9;
    float gg[3][3];
    #pragma unroll
    for (int r = 0; r < 3; ++r)
        #pragma unroll
        for (int s = 0; s < 3; ++s)
            gg[r][s] = quant16f(gp[r * 3 + s]);
    float tr[4][3];
    #pragma unroll
    for (int s = 0; s < 3; ++s) {
        tr[0][s] = gg[0][s];
        tr[1][s] = 0.5f * (gg[0][s] + gg[1][s] + gg[2][s]);
        tr[2][s] = 0.5f * (gg[0][s] - gg[1][s] + gg[2][s]);
        tr[3][s] = gg[2][s];
    }
    #pragma unroll
    for (int a = 0; a < 4; ++a) {
        float u0 = tr[a][0];
        float u1 = 0.5f * (tr[a][0] + tr[a][1] + tr[a][2]);
        float u2 = 0.5f * (tr[a][0] - tr[a][1] + tr[a][2]);
        float u3 = tr[a][2];
        g_U[(a * 4 + 0) * (K_ * C_) + idx] = __float2half_rn(u0);
        g_U[(a * 4 + 1) * (K_ * C_) + idx] = __float2half_rn(u1);
        g_U[(a * 4 + 2) * (K_ * C_) + idx] = __float2half_rn(u2);
        g_U[(a * 4 + 3) * (K_ * C_) + idx] = __float2half_rn(u3);
    }
}

// ---------------- input transform: V = B^T d B (fp32 internal, one rounding) ----------------
// grid 6272 x 256: block = 4 tiles x 64 half2-channels
__global__ __launch_bounds__(256) void wino_in_kernel() {
    const int tid = threadIdx.x;
    const int c2  = tid & 63;                  // half2 channel
    const int p   = blockIdx.x * 4 + (tid >> 6);
    const int n   = p / TPI;
    const int t   = p % TPI;
    const int ty  = t / 28, tx = t % 28;

    const __half2* src = reinterpret_cast<const __half2*>(g_xp)
        + ((size_t)(n * HP_ + 2 * ty) * WP_ + 2 * tx) * (C_ / 2) + c2;
    const int rstr = WP_ * (C_ / 2);           // 3712
    const int cstr = C_ / 2;                   // 64

    float2 d[4][4];
    #pragma unroll
    for (int i = 0; i < 4; ++i)
        #pragma unroll
        for (int j = 0; j < 4; ++j)
            d[i][j] = __half22float2(src[i * rstr + j * cstr]);

    float2 tt[4][4];
    #pragma unroll
    for (int j = 0; j < 4; ++j) {
        tt[0][j] = make_float2(d[0][j].x - d[2][j].x, d[0][j].y - d[2][j].y);
        tt[1][j] = make_float2(d[1][j].x + d[2][j].x, d[1][j].y + d[2][j].y);
        tt[2][j] = make_float2(d[2][j].x - d[1][j].x, d[2][j].y - d[1][j].y);
        tt[3][j] = make_float2(d[1][j].x - d[3][j].x, d[1][j].y - d[3][j].y);
    }
    __half2* dst = reinterpret_cast<__half2*>(g_V) + c2 + (size_t)p * (C_ / 2);
    const size_t plane = (size_t)P_TOT * (C_ / 2);
    #pragma unroll
    for (int a = 0; a < 4; ++a) {
        float2 v0 = make_float2(tt[a][0].x - tt[a][2].x, tt[a][0].y - tt[a][2].y);
        float2 v1 = make_float2(tt[a][1].x + tt[a][2].x, tt[a][1].y + tt[a][2].y);
        float2 v2 = make_float2(tt[a][2].x - tt[a][1].x, tt[a][2].y - tt[a][1].y);
        float2 v3 = make_float2(tt[a][1].x - tt[a][3].x, tt[a][1].y - tt[a][3].y);
        dst[(a * 4 + 0) * plane] = __floats2half2_rn(v0.x, v0.y);
        dst[(a * 4 + 1) * plane] = __floats2half2_rn(v1.x, v1.y);
        dst[(a * 4 + 2) * plane] = __floats2half2_rn(v2.x, v2.y);
        dst[(a * 4 + 3) * plane] = __floats2half2_rn(v3.x, v3.y);
    }
}

// ---------------- batched GEMM: M[xi] = U[xi] (256xC) * V[xi]^T (P x C) ----------------
// grid (196, 16): x = p-block, y = xi. 256 thr, 8 warps (4M x 2N), warp tile 64x64.
__global__ __launch_bounds__(256, 1) void wino_gemm_kernel() {
    extern __shared__ __align__(128) __half smem[];
    const uint32_t sbase = smem_u32(smem);

    const int tid  = threadIdx.x;
    const int lane = tid & 31;
    const int wid  = tid >> 5;
    const int warpM = wid & 3;          // 4 warps along M (64 rows)
    const int warpN = wid >> 2;         // 2 warps along N (64 px)
    const int g  = lane >> 2;
    const int tg = lane & 3;

    const int p0 = blockIdx.x * GBN;
    const int xi = blockIdx.y;

    // A: U[xi], row = tid (256 rows), 8 chunks of 16B per stage (full 64 halves)
    const __half* aG = g_U + ((size_t)xi * K_ + tid) * C_;
    // B: V[xi], 2 thr/row, 4 chunks each (full 64 halves)
    const int bRow = tid >> 1;
    const int bc0  = (tid & 1) * 4;
    const __half* bG = g_V + ((size_t)xi * P_TOT + p0 + bRow) * C_;

    const uint32_t fragSel = ((lane & 15) * PITCH + ((lane >> 4) << 3)) * 2;
    const uint32_t aFragBase = sbase + (uint32_t)(warpM * 64 * PITCH * 2) + fragSel;
    const uint32_t bFragBase = sbase + (uint32_t)SA_BYTES
                             + (uint32_t)(warpN * 64 * PITCH * 2) + fragSel;

    float acc[4][8][4];
    #pragma unroll
    for (int i = 0; i < 4; ++i)
        #pragma unroll
        for (int j = 0; j < 8; ++j)
            #pragma unroll
            for (int e = 0; e < 4; ++e) acc[i][j][e] = 0.0f;

    auto load_stage = [&](int s) {
        const uint32_t sA = sbase + (uint32_t)(s * STAGE_BYTES);
        const uint32_t sB = sA + SA_BYTES;
        const __half* asrc = aG + s * GBK;
        const __half* bsrc = bG + s * GBK;
        #pragma unroll
        for (int c = 0; c < 8; ++c)
            CP16(sA + (tid * PITCH + c * 8) * 2, asrc + c * 8);
        #pragma unroll
        for (int j = 0; j < 4; ++j) {
            const int c = bc0 + j;
            CP16(sB + (bRow * PITCH + c * 8) * 2, bsrc + c * 8);
        }
    };

    auto compute = [&](int buf) {
        const uint32_t off = (uint32_t)(buf * STAGE_BYTES);
        #pragma unroll
        for (int kk = 0; kk < 4; ++kk) {
            const uint32_t kcb = (uint32_t)(kk * 32);
            uint32_t a[4][4], b[8][2];
            #pragma unroll
            for (int i = 0; i < 4; ++i)
                LDSM_X4(a[i][0], a[i][1], a[i][2], a[i][3],
                        aFragBase + off + kcb + i * (16 * PITCH * 2));
            #pragma unroll
            for (int jj = 0; jj < 4; ++jj)
                LDSM_X4(b[2 * jj][0], b[2 * jj + 1][0], b[2 * jj][1], b[2 * jj + 1][1],
                        bFragBase + off + kcb + jj * (16 * PITCH * 2));
            #pragma unroll
            for (int i = 0; i < 4; ++i)
                #pragma unroll
                for (int j = 0; j < 8; ++j)
                    asm volatile(
                        "mma.sync.aligned.m16n8k16.row.col.f32.f16.f16.f32 "
                        "{%0,%1,%2,%3}, {%4,%5,%6,%7}, {%8,%9}, {%0,%1,%2,%3};\n"
                        : "+f"(acc[i][j][0]), "+f"(acc[i][j][1]),
                          "+f"(acc[i][j][2]), "+f"(acc[i][j][3])
                        : "r"(a[i][0]), "r"(a[i][1]), "r"(a[i][2]), "r"(a[i][3]),
                          "r"(b[j][0]), "r"(b[j][1]));
        }
    };

    // K = 128 -> 2 stages
    load_stage(0); CP_COMMIT();
    load_stage(1); CP_COMMIT();
    CP_WAIT1();
    __syncthreads();
    compute(0);
    CP_WAIT0();
    __syncthreads();
    compute(1);

    // epilogue: f32 -> f16 half2 stores into g_M[xi][k][p]
    __half* mBase = g_M + (size_t)xi * (K_ * (size_t)P_TOT);
    #pragma unroll
    for (int i = 0; i < 4; ++i) {
        const int kb = warpM * 64 + i * 16 + g;
        #pragma unroll
        for (int j = 0; j < 8; ++j) {
            const int pc = p0 + warpN * 64 + j * 8 + tg * 2;
            *reinterpret_cast<__half2*>(mBase + (size_t)kb * P_TOT + pc) =
                __floats2half2_rn(acc[i][j][0], acc[i][j][1]);
            *reinterpret_cast<__half2*>(mBase + (size_t)(kb + 8) * P_TOT + pc) =
                __floats2half2_rn(acc[i][j][2], acc[i][j][3]);
        }
    }
}

// ---------------- output transform: Y = A^T M A ----------------
// grid (98, 256): x covers p in blocks of 256, y = k
__global__ __launch_bounds__(256) void wino_out_kernel(float* __restrict__ out) {
    const int p = blockIdx.x * 256 + threadIdx.x;
    const int k = blockIdx.y;
    const size_t kp = (size_t)k * P_TOT + p;

    float m[16];
    #pragma unroll
    for (int xi = 0; xi < 16; ++xi)
        m[xi] = __half2float(g_M[(size_t)xi * (K_ * (size_t)P_TOT) + kp]);

    float s0[4], s1[4];
    #pragma unroll
    for (int b = 0; b < 4; ++b) {
        s0[b] = m[b] + m[4 + b] + m[8 + b];
        s1[b] = m[4 + b] - m[8 + b] - m[12 + b];
    }
    const float y00 = s0[0] + s0[1] + s0[2];
    const float y01 = s0[1] - s0[2] - s0[3];
    const float y10 = s1[0] + s1[1] + s1[2];
    const float y11 = s1[1] - s1[2] - s1[3];

    const int n  = p / TPI;
    const int t  = p % TPI;
    const int ty = t / 28, tx = t % 28;
    float* o = out + (((size_t)(n * K_ + k) * H_) + 2 * ty) * W_ + 2 * tx;
    *reinterpret_cast<float2*>(o)      = make_float2(y00, y01);
    *reinterpret_cast<float2*>(o + W_) = make_float2(y10, y11);
}

extern "C" void kernel_launch(void* const* d_in, const int* in_sizes, int n_in,
                              void* d_out, int out_size) {
    const float* x   = (const float*)d_in[0];   // (32,128,56,56) f32
    const float* wgt = (const float*)d_in[1];   // (256,128,3,3)  f32

    zero_border_kernel<<<N_ * HP_, 128>>>();
    xform_x_kernel<<<dim3(N_, H_), 256>>>(x);
    wino_w_kernel<<<(K_ * C_ + 255) / 256, 256>>>(wgt);
    wino_in_kernel<<<P_TOT / 4, 256>>>();

    static bool attr_set = false;
    if (!attr_set) {
        cudaFuncSetAttribute(wino_gemm_kernel,
                             cudaFuncAttributeMaxDynamicSharedMemorySize, SMEM_TOTAL);
        attr_set = true;
    }
    wino_gemm_kernel<<<dim3(P_TOT / GBN, 16), 256, SMEM_TOTAL>>>();
    wino_out_kernel<<<dim3(P_TOT / 256, K_), 256>>>((float*)d_out);
}

// round 11
// speedup vs baseline: 1.5168x; 1.0574x over previous
#include <cuda_runtime.h>
#include <cuda_fp16.h>
#include <cstdint>

// ---------------- problem constants ----------------
#define N_    32
#define C_    128
#define H_    56
#define W_    56
#define K_    256
#define HW_   3136
#define HP_   58
#define WP_   58
#define TPI   784            // winograd tiles per image (28*28)
#define P_TOT 25088          // 32 * 784

// ---------------- fused GEMM tiling ----------------
#define GBM   128            // k-out per CTA
#define GBN   64             // winograd tiles per CTA
#define GBK   64             // k-halves per stage
#define NST   32             // 16 xi * 2 stages
#define PITCH 72
#define SA_BYTES (GBM * PITCH * 2)              // 18432
#define SB_BYTES (GBN * PITCH * 2)              // 9216
#define STAGE_BYTES (SA_BYTES + SB_BYTES)       // 27648
#define SMEM_TOTAL (3 * STAGE_BYTES)            // 82944

// ---------------- scratch ----------------
__device__ alignas(1024) __half g_xp[(size_t)N_ * HP_ * WP_ * C_];       // padded NHWC fp16
__device__ alignas(1024) __half g_U[16 * K_ * C_];                       // wino weights [xi][k][c]
__device__ alignas(1024) __half g_V[(size_t)16 * P_TOT * C_];            // wino inputs  [xi][p][c]

// ---------------- helpers ----------------
__device__ __forceinline__ uint32_t smem_u32(const void* p) {
    uint32_t a;
    asm("{ .reg .u64 t; cvta.to.shared.u64 t, %1; cvt.u32.u64 %0, t; }" : "=r"(a) : "l"(p));
    return a;
}
#define CP16(dst, src) \
    asm volatile("cp.async.cg.shared.global [%0], [%1], 16;" :: "r"(dst), "l"(src) : "memory")
#define CP_COMMIT() asm volatile("cp.async.commit_group;" ::: "memory")
#define CP_WAIT1()  asm volatile("cp.async.wait_group 1;" ::: "memory")
#define CP_WAIT0()  asm volatile("cp.async.wait_group 0;" ::: "memory")
#define LDSM_X4(r0, r1, r2, r3, addr) \
    asm volatile("ldmatrix.sync.aligned.m8n8.x4.shared.b16 {%0,%1,%2,%3}, [%4];" \
        : "=r"(r0), "=r"(r1), "=r"(r2), "=r"(r3) : "r"(addr))

__device__ __forceinline__ float quant16f(float x) {
    float r = rintf(x * 4096.0f);
    r = fminf(fmaxf(r, -32768.0f), 32767.0f);
    return r * (1.0f / 4096.0f);
}

// ---------------- prepass: quantize + pad input ----------------
__global__ void zero_border_kernel() {
    int b = blockIdx.x;              // 32*58
    int n = b / HP_, hp = b % HP_;
    __half* rowp = g_xp + ((size_t)(n * HP_ + hp)) * WP_ * C_;
    uint4 z = make_uint4(0, 0, 0, 0);
    if (hp == 0 || hp == HP_ - 1) {
        for (int i = threadIdx.x; i < WP_ * C_ / 8; i += blockDim.x)
            reinterpret_cast<uint4*>(rowp)[i] = z;
    } else {
        if (threadIdx.x < 32) {
            int side = threadIdx.x >> 4;
            int q    = threadIdx.x & 15;
            __half* colp = rowp + (side ? (size_t)(WP_ - 1) * C_ : 0);
            reinterpret_cast<uint4*>(colp)[q] = z;
        }
    }
}

__global__ void xform_x_kernel(const float* __restrict__ x) {
    __shared__ __half st[W_ * C_];
    const int n = blockIdx.x, h = blockIdx.y;
    const int tid = threadIdx.x;
    const int c  = tid >> 1;
    const int wh = (tid & 1) * 28;
    const float* src = x + ((size_t)(n * C_ + c) * H_ + h) * W_ + wh;
    #pragma unroll
    for (int j = 0; j < 7; ++j) {
        float4 v = *reinterpret_cast<const float4*>(src + 4 * j);
        int wb = wh + 4 * j;
        st[(wb + 0) * C_ + c] = __float2half_rn(quant16f(v.x));
        st[(wb + 1) * C_ + c] = __float2half_rn(quant16f(v.y));
        st[(wb + 2) * C_ + c] = __float2half_rn(quant16f(v.z));
        st[(wb + 3) * C_ + c] = __float2half_rn(quant16f(v.w));
    }
    __syncthreads();
    __half* dst = g_xp + ((size_t)((n * HP_ + h + 1) * WP_ + 1)) * C_;
    for (int idx = tid; idx < W_ * C_ / 8; idx += 256) {
        int w = idx >> 4, q = idx & 15;
        reinterpret_cast<uint4*>(dst + (size_t)w * C_)[q] =
            reinterpret_cast<const uint4*>(st + w * C_)[q];
    }
}

// ---------------- weight transform: U = G g G^T (exact in f32) ----------------
__global__ void wino_w_kernel(const float* __restrict__ w) {
    int idx = blockIdx.x * 256 + threadIdx.x;      // (k, c)
    if (idx >= K_ * C_) return;
    const float* gp = w + (size_t)idx * 9;
    float gg[3][3];
    #pragma unroll
    for (int r = 0; r < 3; ++r)
        #pragma unroll
        for (int s = 0; s < 3; ++s)
            gg[r][s] = quant16f(gp[r * 3 + s]);
    float tr[4][3];
    #pragma unroll
    for (int s = 0; s < 3; ++s) {
        tr[0][s] = gg[0][s];
        tr[1][s] = 0.5f * (gg[0][s] + gg[1][s] + gg[2][s]);
        tr[2][s] = 0.5f * (gg[0][s] - gg[1][s] + gg[2][s]);
        tr[3][s] = gg[2][s];
    }
    #pragma unroll
    for (int a = 0; a < 4; ++a) {
        float u0 = tr[a][0];
        float u1 = 0.5f * (tr[a][0] + tr[a][1] + tr[a][2]);
        float u2 = 0.5f * (tr[a][0] - tr[a][1] + tr[a][2]);
        float u3 = tr[a][2];
        g_U[(a * 4 + 0) * (K_ * C_) + idx] = __float2half_rn(u0);
        g_U[(a * 4 + 1) * (K_ * C_) + idx] = __float2half_rn(u1);
        g_U[(a * 4 + 2) * (K_ * C_) + idx] = __float2half_rn(u2);
        g_U[(a * 4 + 3) * (K_ * C_) + idx] = __float2half_rn(u3);
    }
}

// ---------------- input transform: V = B^T d B (fp32 internal) ----------------
__global__ __launch_bounds__(256) void wino_in_kernel() {
    const int tid = threadIdx.x;
    const int c2  = tid & 63;
    const int p   = blockIdx.x * 4 + (tid >> 6);
    const int n   = p / TPI;
    const int t   = p % TPI;
    const int ty  = t / 28, tx = t % 28;

    const __half2* src = reinterpret_cast<const __half2*>(g_xp)
        + ((size_t)(n * HP_ + 2 * ty) * WP_ + 2 * tx) * (C_ / 2) + c2;
    const int rstr = WP_ * (C_ / 2);
    const int cstr = C_ / 2;

    float2 d[4][4];
    #pragma unroll
    for (int i = 0; i < 4; ++i)
        #pragma unroll
        for (int j = 0; j < 4; ++j)
            d[i][j] = __half22float2(src[i * rstr + j * cstr]);

    float2 tt[4][4];
    #pragma unroll
    for (int j = 0; j < 4; ++j) {
        tt[0][j] = make_float2(d[0][j].x - d[2][j].x, d[0][j].y - d[2][j].y);
        tt[1][j] = make_float2(d[1][j].x + d[2][j].x, d[1][j].y + d[2][j].y);
        tt[2][j] = make_float2(d[2][j].x - d[1][j].x, d[2][j].y - d[1][j].y);
        tt[3][j] = make_float2(d[1][j].x - d[3][j].x, d[1][j].y - d[3][j].y);
    }
    __half2* dst = reinterpret_cast<__half2*>(g_V) + c2 + (size_t)p * (C_ / 2);
    const size_t plane = (size_t)P_TOT * (C_ / 2);
    #pragma unroll
    for (int a = 0; a < 4; ++a) {
        float2 v0 = make_float2(tt[a][0].x - tt[a][2].x, tt[a][0].y - tt[a][2].y);
        float2 v1 = make_float2(tt[a][1].x + tt[a][2].x, tt[a][1].y + tt[a][2].y);
        float2 v2 = make_float2(tt[a][2].x - tt[a][1].x, tt[a][2].y - tt[a][1].y);
        float2 v3 = make_float2(tt[a][1].x - tt[a][3].x, tt[a][1].y - tt[a][3].y);
        dst[(a * 4 + 0) * plane] = __floats2half2_rn(v0.x, v0.y);
        dst[(a * 4 + 1) * plane] = __floats2half2_rn(v1.x, v1.y);
        dst[(a * 4 + 2) * plane] = __floats2half2_rn(v2.x, v2.y);
        dst[(a * 4 + 3) * plane] = __floats2half2_rn(v3.x, v3.y);
    }
}

// ---------------- fused GEMM + output transform ----------------
// grid (392, 2), 256 threads, 8 warps (4M x 2N), warp tile 32x32.
// CTA: 128 k-out x 64 wino tiles; loops 16 xi (32 stages of BK=64),
// folds each xi's fp32 M-tile into Y accumulators, writes NCHW at the end.
__global__ __launch_bounds__(256, 1) void wino_fused_kernel(float* __restrict__ out) {
    extern __shared__ __align__(128) __half smem[];
    const uint32_t sbase = smem_u32(smem);

    const int tid  = threadIdx.x;
    const int lane = tid & 31;
    const int wid  = tid >> 5;
    const int warpM = wid & 3;          // 4 warps along M (32 rows)
    const int warpN = wid >> 2;         // 2 warps along N (32 tiles)
    const int g  = lane >> 2;
    const int tg = lane & 3;

    const int p0 = blockIdx.x * GBN;
    const int k0 = blockIdx.y * GBM;

    // loader mapping
    const int aRow = tid >> 1;                    // 128 rows, 2 thr/row
    const int ac0  = (tid & 1) * 4;               // 4 contiguous chunks
    const int bRow = tid >> 2;                    // 64 rows, 4 thr/row
    const int bc0  = (tid & 3) * 2;               // 2 contiguous chunks
    const __half* aGbase = g_U + (size_t)(k0 + aRow) * C_ + ac0 * 8;
    const __half* bGbase = g_V + (size_t)(p0 + bRow) * C_ + bc0 * 8;

    // fragment ldmatrix bases
    const uint32_t fragSel = ((lane & 15) * PITCH + ((lane >> 4) << 3)) * 2;
    const uint32_t aFragBase = sbase + (uint32_t)(warpM * 32 * PITCH * 2) + fragSel;
    const uint32_t bFragBase = sbase + (uint32_t)SA_BYTES
                             + (uint32_t)(warpN * 32 * PITCH * 2) + fragSel;

    float acc[2][4][4];
    float Y[2][4][4][4];
    #pragma unroll
    for (int i = 0; i < 2; ++i)
        #pragma unroll
        for (int j = 0; j < 4; ++j)
            #pragma unroll
            for (int e = 0; e < 4; ++e) {
                acc[i][j][e] = 0.0f;
                #pragma unroll
                for (int q = 0; q < 4; ++q) Y[i][j][e][q] = 0.0f;
            }

    auto load_stage = [&](int s) {
        const uint32_t sA = sbase + (uint32_t)((s % 3) * STAGE_BYTES);
        const uint32_t sB = sA + SA_BYTES;
        const int xi = s >> 1;
        const int hf = (s & 1) << 6;              // 0 or 64 halves in C
        const __half* asrc = aGbase + (size_t)xi * (K_ * C_) + hf;
        const __half* bsrc = bGbase + (size_t)xi * ((size_t)P_TOT * C_) + hf;
        #pragma unroll
        for (int j = 0; j < 4; ++j)
            CP16(sA + (aRow * PITCH + (ac0 + j) * 8) * 2, asrc + j * 8);
        #pragma unroll
        for (int j = 0; j < 2; ++j)
            CP16(sB + (bRow * PITCH + (bc0 + j) * 8) * 2, bsrc + j * 8);
    };

    auto compute = [&](int buf) {
        const uint32_t off = (uint32_t)(buf * STAGE_BYTES);
        #pragma unroll
        for (int kk = 0; kk < 4; ++kk) {
            const uint32_t kcb = (uint32_t)(kk * 32);
            uint32_t a[2][4], b[4][2];
            #pragma unroll
            for (int i = 0; i < 2; ++i)
                LDSM_X4(a[i][0], a[i][1], a[i][2], a[i][3],
                        aFragBase + off + kcb + i * (16 * PITCH * 2));
            #pragma unroll
            for (int jj = 0; jj < 2; ++jj)
                LDSM_X4(b[2 * jj][0], b[2 * jj + 1][0], b[2 * jj][1], b[2 * jj + 1][1],
                        bFragBase + off + kcb + jj * (16 * PITCH * 2));
            #pragma unroll
            for (int i = 0; i < 2; ++i)
                #pragma unroll
                for (int j = 0; j < 4; ++j)
                    asm volatile(
                        "mma.sync.aligned.m16n8k16.row.col.f32.f16.f16.f32 "
                        "{%0,%1,%2,%3}, {%4,%5,%6,%7}, {%8,%9}, {%0,%1,%2,%3};\n"
                        : "+f"(acc[i][j][0]), "+f"(acc[i][j][1]),
                          "+f"(acc[i][j][2]), "+f"(acc[i][j][3])
                        : "r"(a[i][0]), "r"(a[i][1]), "r"(a[i][2]), "r"(a[i][3]),
                          "r"(b[j][0]), "r"(b[j][1]));
        }
    };

    // ---- pipeline across all 16 xi (32 stages) ----
    load_stage(0); CP_COMMIT();
    load_stage(1); CP_COMMIT();

    #pragma unroll 1
    for (int s = 0; s < NST; ++s) {
        if (s < NST - 1) { CP_WAIT1(); } else { CP_WAIT0(); }
        __syncthreads();
        if (s + 2 < NST) { load_stage(s + 2); CP_COMMIT(); }
        compute(s % 3);

        if (s & 1) {
            // fold xi's M into Y:  Y_ab += AT[a][iy] * AT[b][jx] * m
            const int xi = s >> 1;
            const int iy = xi >> 2, jx = xi & 3;
            const float a0 = (iy < 3) ? 1.0f : 0.0f;
            const float a1 = (iy == 0) ? 0.0f : ((iy == 1) ? 1.0f : -1.0f);
            const float b0 = (jx < 3) ? 1.0f : 0.0f;
            const float b1 = (jx == 0) ? 0.0f : ((jx == 1) ? 1.0f : -1.0f);
            const float g00 = a0 * b0, g01 = a0 * b1, g10 = a1 * b0, g11 = a1 * b1;
            #pragma unroll
            for (int i = 0; i < 2; ++i)
                #pragma unroll
                for (int j = 0; j < 4; ++j)
                    #pragma unroll
                    for (int e = 0; e < 4; ++e) {
                        const float m = acc[i][j][e];
                        Y[i][j][e][0] += g00 * m;
                        Y[i][j][e][1] += g01 * m;
                        Y[i][j][e][2] += g10 * m;
                        Y[i][j][e][3] += g11 * m;
                        acc[i][j][e] = 0.0f;
                    }
        }
    }

    // ---- epilogue: Y -> NCHW output (2x2 patch per cell) ----
    #pragma unroll
    for (int i = 0; i < 2; ++i) {
        #pragma unroll
        for (int j = 0; j < 4; ++j) {
            #pragma unroll
            for (int e = 0; e < 4; ++e) {
                const int k = k0 + warpM * 32 + i * 16 + g + ((e >> 1) << 3);
                const int p = p0 + warpN * 32 + j * 8 + tg * 2 + (e & 1);
                const int n  = p / TPI;
                const int t  = p % TPI;
                const int ty = t / 28, tx = t % 28;
                float* o = out + (((size_t)(n * K_ + k) * H_) + 2 * ty) * W_ + 2 * tx;
                *reinterpret_cast<float2*>(o)      = make_float2(Y[i][j][e][0], Y[i][j][e][1]);
                *reinterpret_cast<float2*>(o + W_) = make_float2(Y[i][j][e][2], Y[i][j][e][3]);
            }
        }
    }
}

extern "C" void kernel_launch(void* const* d_in, const int* in_sizes, int n_in,
                              void* d_out, int out_size) {
    const float* x   = (const float*)d_in[0];   // (32,128,56,56) f32
    const float* wgt = (const float*)d_in[1];   // (256,128,3,3)  f32

    zero_border_kernel<<<N_ * HP_, 128>>>();
    xform_x_kernel<<<dim3(N_, H_), 256>>>(x);
    wino_w_kernel<<<(K_ * C_ + 255) / 256, 256>>>(wgt);
    wino_in_kernel<<<P_TOT / 4, 256>>>();

    static bool attr_set = false;
    if (!attr_set) {
        cudaFuncSetAttribute(wino_fused_kernel,
                             cudaFuncAttributeMaxDynamicSharedMemorySize, SMEM_TOTAL);
        attr_set = true;
    }
    wino_fused_kernel<<<dim3(P_TOT / GBN, K_ / GBM), 256, SMEM_TOTAL>>>((float*)d_out);
}